// round 2
// baseline (speedup 1.0000x reference)
#include <cuda_runtime.h>
#include <cuda_bf16.h>
#include <cstdint>

#define MAX_NODES 100000
#define D_IN 512
#define D_OUT 128

// ---------------- device scratch (no allocations allowed) ----------------
__device__ float g_h[(size_t)MAX_NODES * D_OUT];          // 51.2 MB: h = X @ W
__device__ __nv_bfloat16 g_WtH[D_OUT * D_IN];             // W transposed [n][k], hi
__device__ __nv_bfloat16 g_WtL[D_OUT * D_IN];             // W transposed [n][k], lo
__device__ int g_idx64;                                   // 1 if edge indices are int64

// ---------------- helpers ----------------
__device__ __forceinline__ void bf16split(float x, __nv_bfloat16& hi, __nv_bfloat16& lo) {
    hi = __float2bfloat16(x);
    lo = __float2bfloat16(x - __bfloat162float(hi));
}

__device__ __forceinline__ void mma_bf16(float* c, const uint32_t* a, const uint32_t* b) {
    asm volatile(
        "mma.sync.aligned.m16n8k16.row.col.f32.bf16.bf16.f32 "
        "{%0,%1,%2,%3}, {%4,%5,%6,%7}, {%8,%9}, {%0,%1,%2,%3};\n"
        : "+f"(c[0]), "+f"(c[1]), "+f"(c[2]), "+f"(c[3])
        : "r"(a[0]), "r"(a[1]), "r"(a[2]), "r"(a[3]), "r"(b[0]), "r"(b[1]));
}

// ---------------- kernel 0: split + transpose W once per launch ----------------
__global__ void prep_w_kernel(const float* __restrict__ W) {
    int i = blockIdx.x * blockDim.x + threadIdx.x;   // 512*128 = 65536
    if (i < D_IN * D_OUT) {
        int k = i >> 7;          // row in W  (K)
        int n = i & 127;         // col in W  (N)
        float x = W[i];
        __nv_bfloat16 h, l;
        bf16split(x, h, l);
        g_WtH[n * D_IN + k] = h;
        g_WtL[n * D_IN + k] = l;
    }
}

// ---------------- kernel 1: detect int64 vs int32 edge indices ----------------
// int64 (LE, values < 2^31): every odd 32-bit word is 0. Sample ~4096 odd words.
__global__ void detect_idx_kernel(const unsigned int* __restrict__ s,
                                  const unsigned int* __restrict__ d, int nwords) {
    __shared__ unsigned int sh[256];
    unsigned int v = 0;
    #pragma unroll
    for (int k = 0; k < 8; k++) {
        int pos = (threadIdx.x * 8 + k) * 312 + 1;   // odd positions, spread over array
        if (pos < nwords) v |= s[pos] | d[pos];
    }
    sh[threadIdx.x] = v;
    __syncthreads();
    for (int off = 128; off; off >>= 1) {
        if (threadIdx.x < off) sh[threadIdx.x] |= sh[threadIdx.x + off];
        __syncthreads();
    }
    if (threadIdx.x == 0) g_idx64 = (sh[0] == 0u) ? 1 : 0;
}

// ---------------- kernel 2: init out with bias ----------------
__global__ void init_out_kernel(float4* __restrict__ out, const float* __restrict__ bias, int n4) {
    int i = blockIdx.x * blockDim.x + threadIdx.x;
    if (i < n4) {
        out[i] = ((const float4*)bias)[i & 31];   // D_OUT/4 = 32
    }
}

// ---------------- kernel 3: h = X @ W  (bf16x3 split GEMM, fp32 accuracy) ----------------
// 2-stage software pipeline: next K-slab's global loads are issued into
// registers before the current slab's MMA loop, committed to smem after.
#define BM 128
#define BN 128
#define BK 32
#define KPAD 40   // row stride 80B = 20 banks -> conflict-free mma frag loads

__global__ __launch_bounds__(256) void gemm_bf16x3_kernel(
    const float* __restrict__ A, int M) {
    __shared__ __nv_bfloat16 AsH[BM][KPAD];
    __shared__ __nv_bfloat16 AsL[BM][KPAD];
    __shared__ __nv_bfloat16 BsH[BN][KPAD];   // stored [n][k]
    __shared__ __nv_bfloat16 BsL[BN][KPAD];

    const int tid  = threadIdx.x;
    const int lane = tid & 31;
    const int warp = tid >> 5;
    const int wm   = warp >> 2;       // 0..1   (M dim, 64 rows each)
    const int wn   = warp & 3;        // 0..3   (N dim, 32 cols each)
    const int lr   = lane >> 2;       // 0..7
    const int lq   = lane & 3;        // 0..3
    const int m_block = blockIdx.x * BM;

    // Per-thread staging slots for the pipeline
    // A: 4 float4 (rows row_a[it], col c_a[it]); B: 2x (uint4 H + uint4 L)
    const int rowA0 = tid >> 3;            // it stride: +32 rows per it? no: idx=tid+it*256
    (void)rowA0;

    float acc[4][4][4];
    #pragma unroll
    for (int i = 0; i < 4; i++)
        #pragma unroll
        for (int j = 0; j < 4; j++)
            #pragma unroll
            for (int k = 0; k < 4; k++) acc[i][j][k] = 0.f;

    float4 pa[4];
    uint4  pbH[2], pbL[2];

    // ---- prologue: load slab kc=0 into registers ----
    {
        const int kc = 0;
        #pragma unroll
        for (int it = 0; it < 4; it++) {
            int idx = tid + it * 256;
            int row = idx >> 3;
            int c   = (idx & 7) * 4;
            int gm  = m_block + row;
            pa[it] = make_float4(0.f, 0.f, 0.f, 0.f);
            if (gm < M) pa[it] = *(const float4*)(A + (size_t)gm * D_IN + kc + c);
        }
        #pragma unroll
        for (int it = 0; it < 2; it++) {
            int idx = tid + it * 256;
            int n   = idx >> 2;
            int kg  = (idx & 3) * 8;
            pbH[it] = *(const uint4*)(g_WtH + (size_t)n * D_IN + kc + kg);
            pbL[it] = *(const uint4*)(g_WtL + (size_t)n * D_IN + kc + kg);
        }
    }

    for (int kc = 0; kc < D_IN; kc += BK) {
        // ---- commit staged slab to smem ----
        #pragma unroll
        for (int it = 0; it < 4; it++) {
            int idx = tid + it * 256;
            int row = idx >> 3;
            int c   = (idx & 7) * 4;
            __nv_bfloat16 h0, l0, h1, l1, h2, l2, h3, l3;
            bf16split(pa[it].x, h0, l0); bf16split(pa[it].y, h1, l1);
            bf16split(pa[it].z, h2, l2); bf16split(pa[it].w, h3, l3);
            *(__nv_bfloat162*)&AsH[row][c]     = __halves2bfloat162(h0, h1);
            *(__nv_bfloat162*)&AsH[row][c + 2] = __halves2bfloat162(h2, h3);
            *(__nv_bfloat162*)&AsL[row][c]     = __halves2bfloat162(l0, l1);
            *(__nv_bfloat162*)&AsL[row][c + 2] = __halves2bfloat162(l2, l3);
        }
        #pragma unroll
        for (int it = 0; it < 2; it++) {
            int idx = tid + it * 256;
            int n   = idx >> 2;
            int kg  = (idx & 3) * 8;
            *(uint4*)&BsH[n][kg] = pbH[it];
            *(uint4*)&BsL[n][kg] = pbL[it];
        }
        __syncthreads();

        // ---- issue next slab's global loads (overlap with MMA below) ----
        const int kn = kc + BK;
        if (kn < D_IN) {
            #pragma unroll
            for (int it = 0; it < 4; it++) {
                int idx = tid + it * 256;
                int row = idx >> 3;
                int c   = (idx & 7) * 4;
                int gm  = m_block + row;
                pa[it] = make_float4(0.f, 0.f, 0.f, 0.f);
                if (gm < M) pa[it] = *(const float4*)(A + (size_t)gm * D_IN + kn + c);
            }
            #pragma unroll
            for (int it = 0; it < 2; it++) {
                int idx = tid + it * 256;
                int n   = idx >> 2;
                int kg  = (idx & 3) * 8;
                pbH[it] = *(const uint4*)(g_WtH + (size_t)n * D_IN + kn + kg);
                pbL[it] = *(const uint4*)(g_WtL + (size_t)n * D_IN + kn + kg);
            }
        }

        // ---- MMA over current slab ----
        #pragma unroll
        for (int kk = 0; kk < BK; kk += 16) {
            uint32_t bH[4][2], bL[4][2];
            #pragma unroll
            for (int j = 0; j < 4; j++) {
                int n = wn * 32 + j * 8 + lr;
                bH[j][0] = *(const uint32_t*)&BsH[n][kk + lq * 2];
                bH[j][1] = *(const uint32_t*)&BsH[n][kk + lq * 2 + 8];
                bL[j][0] = *(const uint32_t*)&BsL[n][kk + lq * 2];
                bL[j][1] = *(const uint32_t*)&BsL[n][kk + lq * 2 + 8];
            }
            #pragma unroll
            for (int i = 0; i < 4; i++) {
                int r = wm * 64 + i * 16 + lr;
                uint32_t aH[4], aL[4];
                aH[0] = *(const uint32_t*)&AsH[r][kk + lq * 2];
                aH[1] = *(const uint32_t*)&AsH[r + 8][kk + lq * 2];
                aH[2] = *(const uint32_t*)&AsH[r][kk + lq * 2 + 8];
                aH[3] = *(const uint32_t*)&AsH[r + 8][kk + lq * 2 + 8];
                aL[0] = *(const uint32_t*)&AsL[r][kk + lq * 2];
                aL[1] = *(const uint32_t*)&AsL[r + 8][kk + lq * 2];
                aL[2] = *(const uint32_t*)&AsL[r][kk + lq * 2 + 8];
                aL[3] = *(const uint32_t*)&AsL[r + 8][kk + lq * 2 + 8];
                #pragma unroll
                for (int j = 0; j < 4; j++) {
                    mma_bf16(acc[i][j], aH, bH[j]);   // hi*hi
                    mma_bf16(acc[i][j], aH, bL[j]);   // hi*lo
                    mma_bf16(acc[i][j], aL, bH[j]);   // lo*hi
                }
            }
        }
        __syncthreads();
    }

    // --- epilogue: write h ---
    #pragma unroll
    for (int i = 0; i < 4; i++) {
        int r0 = m_block + wm * 64 + i * 16 + lr;
        #pragma unroll
        for (int j = 0; j < 4; j++) {
            int cB = wn * 32 + j * 8 + lq * 2;
            if (r0 < M)
                *(float2*)(g_h + (size_t)r0 * D_OUT + cB) =
                    make_float2(acc[i][j][0], acc[i][j][1]);
            if (r0 + 8 < M)
                *(float2*)(g_h + (size_t)(r0 + 8) * D_OUT + cB) =
                    make_float2(acc[i][j][2], acc[i][j][3]);
        }
    }
}

// ---------------- kernel 4: edge scatter: out[dst] += w * h[src] ----------------
// One warp per edge; lane handles 4 floats; vectorized RED (red.global.add.v4.f32).
__global__ __launch_bounds__(256) void edge_scatter_kernel(
    const void* __restrict__ esrc, const void* __restrict__ edst,
    const float* __restrict__ ew, float* __restrict__ out, int E) {
    int gw   = (int)((blockIdx.x * 256u + threadIdx.x) >> 5);
    int lane = threadIdx.x & 31;
    if (gw >= E) return;

    long long s, d;
    if (g_idx64) {
        s = ((const long long*)esrc)[gw];
        d = ((const long long*)edst)[gw];
    } else {
        s = (long long)((const int*)esrc)[gw];
        d = (long long)((const int*)edst)[gw];
    }
    float w = __ldg(ew + gw);

    const float4 v = *(const float4*)(g_h + (size_t)s * D_OUT + lane * 4);
    float4 m;
    m.x = v.x * w; m.y = v.y * w; m.z = v.z * w; m.w = v.w * w;

    float* p = out + (size_t)d * D_OUT + lane * 4;
    asm volatile("red.global.add.v4.f32 [%0], {%1, %2, %3, %4};"
                 :: "l"(p), "f"(m.x), "f"(m.y), "f"(m.z), "f"(m.w)
                 : "memory");
}

// ---------------- launch ----------------
extern "C" void kernel_launch(void* const* d_in, const int* in_sizes, int n_in,
                              void* d_out, int out_size) {
    const float* features = (const float*)d_in[0];
    const void*  esrc     = d_in[1];
    const void*  edst     = d_in[2];
    const float* eweight  = (const float*)d_in[3];
    const float* W        = (const float*)d_in[4];
    const float* bias     = (const float*)d_in[5];
    float*       out      = (float*)d_out;

    const int M = in_sizes[0] / D_IN;     // 100000 nodes
    const int E = in_sizes[3];            // 640000 edges (float weight count: dtype-safe)
    const int n4 = out_size / 4;          // out float4 count

    // 0: split + transpose W to bf16 hi/lo, [n][k] layout
    prep_w_kernel<<<(D_IN * D_OUT + 255) / 256, 256>>>(W);
    // 1: probe edge index dtype (int32 vs int64)
    detect_idx_kernel<<<1, 256>>>((const unsigned int*)esrc, (const unsigned int*)edst, E);
    // 2: out = bias (broadcast)
    init_out_kernel<<<(n4 + 255) / 256, 256>>>((float4*)out, bias, n4);
    // 3: h = X @ W  (bf16x3 tensor-core GEMM, fp32 accuracy, 2-stage pipeline)
    gemm_bf16x3_kernel<<<(M + BM - 1) / BM, 256>>>(features, M);
    // 4: out[dst] += w * h[src]  (vectorized global reductions)
    edge_scatter_kernel<<<(E * 32 + 255) / 256, 256>>>(esrc, edst, eweight, out, E);
}

// round 7
// speedup vs baseline: 1.1082x; 1.1082x over previous
#include <cuda_runtime.h>
#include <cuda_bf16.h>
#include <cstdint>

#define MAX_NODES 100000
#define D_IN 512
#define D_OUT 128

// ---------------- device scratch (no allocations allowed) ----------------
__device__ float g_h[(size_t)MAX_NODES * D_OUT];          // 51.2 MB: h = X @ W
__device__ __nv_bfloat16 g_WtH[D_OUT * D_IN];             // W transposed [n][k], hi
__device__ __nv_bfloat16 g_WtL[D_OUT * D_IN];             // W transposed [n][k], lo
__device__ int g_idx64;                                   // 1 if edge indices are int64

// ---------------- helpers ----------------
__device__ __forceinline__ void bf16split(float x, __nv_bfloat16& hi, __nv_bfloat16& lo) {
    hi = __float2bfloat16(x);
    lo = __float2bfloat16(x - __bfloat162float(hi));
}
__device__ __forceinline__ uint32_t smem_u32(const void* p) {
    uint32_t a;
    asm("{ .reg .u64 t; cvta.to.shared.u64 t, %1; cvt.u32.u64 %0, t; }" : "=r"(a) : "l"(p));
    return a;
}
__device__ __forceinline__ void mma_bf16(float* c, const uint32_t* a, const uint32_t* b) {
    asm volatile(
        "mma.sync.aligned.m16n8k16.row.col.f32.bf16.bf16.f32 "
        "{%0,%1,%2,%3}, {%4,%5,%6,%7}, {%8,%9}, {%0,%1,%2,%3};\n"
        : "+f"(c[0]), "+f"(c[1]), "+f"(c[2]), "+f"(c[3])
        : "r"(a[0]), "r"(a[1]), "r"(a[2]), "r"(a[3]), "r"(b[0]), "r"(b[1]));
}
__device__ __forceinline__ void ldsm_x4(uint32_t* r, uint32_t addr) {
    asm volatile("ldmatrix.sync.aligned.m8n8.x4.shared.b16 {%0,%1,%2,%3}, [%4];"
                 : "=r"(r[0]), "=r"(r[1]), "=r"(r[2]), "=r"(r[3]) : "r"(addr));
}

// ---------------- kernel 0: split + transpose W once per launch ----------------
__global__ void prep_w_kernel(const float* __restrict__ W) {
    int i = blockIdx.x * blockDim.x + threadIdx.x;   // 512*128 = 65536
    if (i < D_IN * D_OUT) {
        int k = i >> 7;          // row in W  (K)
        int n = i & 127;         // col in W  (N)
        float x = W[i];
        __nv_bfloat16 h, l;
        bf16split(x, h, l);
        g_WtH[n * D_IN + k] = h;
        g_WtL[n * D_IN + k] = l;
    }
}

// ---------------- kernel 1: detect int64 vs int32 edge indices ----------------
__global__ void detect_idx_kernel(const unsigned int* __restrict__ s,
                                  const unsigned int* __restrict__ d, int nwords) {
    __shared__ unsigned int sh[256];
    unsigned int v = 0;
    #pragma unroll
    for (int k = 0; k < 8; k++) {
        int pos = (threadIdx.x * 8 + k) * 312 + 1;   // odd positions, spread over array
        if (pos < nwords) v |= s[pos] | d[pos];
    }
    sh[threadIdx.x] = v;
    __syncthreads();
    for (int off = 128; off; off >>= 1) {
        if (threadIdx.x < off) sh[threadIdx.x] |= sh[threadIdx.x + off];
        __syncthreads();
    }
    if (threadIdx.x == 0) g_idx64 = (sh[0] == 0u) ? 1 : 0;
}

// ---------------- kernel 2: init out with bias ----------------
__global__ void init_out_kernel(float4* __restrict__ out, const float* __restrict__ bias, int n4) {
    int i = blockIdx.x * blockDim.x + threadIdx.x;
    if (i < n4) out[i] = ((const float4*)bias)[i & 31];   // D_OUT/4 = 32
}

// ---------------- kernel 3: h = X @ W  (bf16x3 split GEMM, ldmatrix, 2 CTA/SM) ----------------
#define BM 128
#define BN 128
#define BK 32
#define KPAD 40   // row stride 80B = 20 banks -> conflict-free frag/ldmatrix loads

__global__ __launch_bounds__(256, 2) void gemm_bf16x3_kernel(
    const float* __restrict__ A, int M) {
    __shared__ __nv_bfloat16 AsH[BM][KPAD];
    __shared__ __nv_bfloat16 AsL[BM][KPAD];
    __shared__ __nv_bfloat16 BsH[BN][KPAD];   // stored [n][k]
    __shared__ __nv_bfloat16 BsL[BN][KPAD];

    const int tid  = threadIdx.x;
    const int lane = tid & 31;
    const int warp = tid >> 5;
    const int wm   = warp >> 2;       // 0..1   (M dim, 64 rows each)
    const int wn   = warp & 3;        // 0..3   (N dim, 32 cols each)
    const int m_block = blockIdx.x * BM;

    // ldmatrix lane addressing:
    //  A: row = wm*64 + i*16 + (lane&15), col = kk + (lane>>4)*8
    //     -> m0..m3 = {a0,a1,a2,a3} of mma.m16n8k16
    //  B: n = wn*32 + (lane>>4)*8 + (lane&7), col = kk + ((lane>>3)&1)*8
    //     -> r0..r3 = {b0,b1} of j-group, {b0,b1} of j-group+1
    const int a_row  = wm * 64 + (lane & 15);
    const int a_col  = (lane >> 4) * 8;
    const int b_row  = wn * 32 + ((lane >> 4) * 8) + (lane & 7);
    const int b_col  = ((lane >> 3) & 1) * 8;

    const uint32_t aH_base = smem_u32(&AsH[a_row][a_col]);
    const uint32_t aL_base = smem_u32(&AsL[a_row][a_col]);
    const uint32_t bH_base = smem_u32(&BsH[b_row][b_col]);
    const uint32_t bL_base = smem_u32(&BsL[b_row][b_col]);

    float acc[4][4][4];
    #pragma unroll
    for (int i = 0; i < 4; i++)
        #pragma unroll
        for (int j = 0; j < 4; j++)
            #pragma unroll
            for (int k = 0; k < 4; k++) acc[i][j][k] = 0.f;

    // A prefetch registers (B loads direct: small, L2-resident)
    float4 pa[4];
    {
        #pragma unroll
        for (int it = 0; it < 4; it++) {
            int idx = tid + it * 256;
            int row = idx >> 3;
            int c   = (idx & 7) * 4;
            int gm  = m_block + row;
            pa[it] = make_float4(0.f, 0.f, 0.f, 0.f);
            if (gm < M) pa[it] = *(const float4*)(A + (size_t)gm * D_IN + c);
        }
    }

    for (int kc = 0; kc < D_IN; kc += BK) {
        // ---- commit staged A slab to smem (split hi/lo) ----
        #pragma unroll
        for (int it = 0; it < 4; it++) {
            int idx = tid + it * 256;
            int row = idx >> 3;
            int c   = (idx & 7) * 4;
            __nv_bfloat16 h0, l0, h1, l1, h2, l2, h3, l3;
            bf16split(pa[it].x, h0, l0); bf16split(pa[it].y, h1, l1);
            bf16split(pa[it].z, h2, l2); bf16split(pa[it].w, h3, l3);
            *(__nv_bfloat162*)&AsH[row][c]     = __halves2bfloat162(h0, h1);
            *(__nv_bfloat162*)&AsH[row][c + 2] = __halves2bfloat162(h2, h3);
            *(__nv_bfloat162*)&AsL[row][c]     = __halves2bfloat162(l0, l1);
            *(__nv_bfloat162*)&AsL[row][c + 2] = __halves2bfloat162(l2, l3);
        }
        // ---- stage B slab direct (16B vectors) ----
        #pragma unroll
        for (int it = 0; it < 2; it++) {
            int idx = tid + it * 256;
            int n   = idx >> 2;
            int kg  = (idx & 3) * 8;
            *(uint4*)&BsH[n][kg] = *(const uint4*)(g_WtH + (size_t)n * D_IN + kc + kg);
            *(uint4*)&BsL[n][kg] = *(const uint4*)(g_WtL + (size_t)n * D_IN + kc + kg);
        }
        __syncthreads();

        // ---- prefetch next A slab (overlaps with MMA below) ----
        const int kn = kc + BK;
        if (kn < D_IN) {
            #pragma unroll
            for (int it = 0; it < 4; it++) {
                int idx = tid + it * 256;
                int row = idx >> 3;
                int c   = (idx & 7) * 4;
                int gm  = m_block + row;
                pa[it] = make_float4(0.f, 0.f, 0.f, 0.f);
                if (gm < M) pa[it] = *(const float4*)(A + (size_t)gm * D_IN + kn + c);
            }
        }

        // ---- MMA over current slab ----
        #pragma unroll
        for (int kk = 0; kk < BK; kk += 16) {
            const uint32_t koff = (uint32_t)(kk * 2);   // bytes
            uint32_t bH[8], bL[8];      // [j pair][{b0,b1}] packed as j*2+reg
            ldsm_x4(bH + 0, bH_base + koff);                         // j=0,1
            ldsm_x4(bH + 4, bH_base + koff + 16 * KPAD * 2);         // j=2,3
            ldsm_x4(bL + 0, bL_base + koff);
            ldsm_x4(bL + 4, bL_base + koff + 16 * KPAD * 2);
            #pragma unroll
            for (int i = 0; i < 4; i++) {
                const uint32_t aoff = koff + (uint32_t)(i * 16 * KPAD * 2);
                uint32_t aH[4], aL[4];
                ldsm_x4(aH, aH_base + aoff);
                ldsm_x4(aL, aL_base + aoff);
                #pragma unroll
                for (int j = 0; j < 4; j++) {
                    mma_bf16(acc[i][j], aH, bH + j * 2);   // hi*hi
                    mma_bf16(acc[i][j], aH, bL + j * 2);   // hi*lo
                    mma_bf16(acc[i][j], aL, bH + j * 2);   // lo*hi
                }
            }
        }
        __syncthreads();
    }

    // --- epilogue: write h ---
    const int lr = lane >> 2;
    const int lq = lane & 3;
    #pragma unroll
    for (int i = 0; i < 4; i++) {
        int r0 = m_block + wm * 64 + i * 16 + lr;
        #pragma unroll
        for (int j = 0; j < 4; j++) {
            int cB = wn * 32 + j * 8 + lq * 2;
            if (r0 < M)
                *(float2*)(g_h + (size_t)r0 * D_OUT + cB) =
                    make_float2(acc[i][j][0], acc[i][j][1]);
            if (r0 + 8 < M)
                *(float2*)(g_h + (size_t)(r0 + 8) * D_OUT + cB) =
                    make_float2(acc[i][j][2], acc[i][j][3]);
        }
    }
}

// ---------------- kernel 4: edge scatter: out[dst] += w * h[src] ----------------
__global__ __launch_bounds__(256) void edge_scatter_kernel(
    const void* __restrict__ esrc, const void* __restrict__ edst,
    const float* __restrict__ ew, float* __restrict__ out, int E) {
    int gw   = (int)((blockIdx.x * 256u + threadIdx.x) >> 5);
    int lane = threadIdx.x & 31;
    if (gw >= E) return;

    long long s, d;
    if (g_idx64) {
        s = ((const long long*)esrc)[gw];
        d = ((const long long*)edst)[gw];
    } else {
        s = (long long)((const int*)esrc)[gw];
        d = (long long)((const int*)edst)[gw];
    }
    float w = __ldg(ew + gw);

    const float4 v = *(const float4*)(g_h + (size_t)s * D_OUT + lane * 4);
    float4 m;
    m.x = v.x * w; m.y = v.y * w; m.z = v.z * w; m.w = v.w * w;

    float* p = out + (size_t)d * D_OUT + lane * 4;
    asm volatile("red.global.add.v4.f32 [%0], {%1, %2, %3, %4};"
                 :: "l"(p), "f"(m.x), "f"(m.y), "f"(m.z), "f"(m.w)
                 : "memory");
}

// ---------------- launch ----------------
extern "C" void kernel_launch(void* const* d_in, const int* in_sizes, int n_in,
                              void* d_out, int out_size) {
    const float* features = (const float*)d_in[0];
    const void*  esrc     = d_in[1];
    const void*  edst     = d_in[2];
    const float* eweight  = (const float*)d_in[3];
    const float* W        = (const float*)d_in[4];
    const float* bias     = (const float*)d_in[5];
    float*       out      = (float*)d_out;

    const int M  = in_sizes[0] / D_IN;   // 100000
    const int E  = in_sizes[3];          // 640000
    const int n4 = out_size / 4;

    prep_w_kernel<<<(D_IN * D_OUT + 255) / 256, 256>>>(W);
    detect_idx_kernel<<<1, 256>>>((const unsigned int*)esrc, (const unsigned int*)edst, E);
    init_out_kernel<<<(n4 + 255) / 256, 256>>>((float4*)out, bias, n4);
    gemm_bf16x3_kernel<<<(M + BM - 1) / BM, 256>>>(features, M);
    edge_scatter_kernel<<<(E * 32 + 255) / 256, 256>>>(esrc, edst, eweight, out, E);
}